// round 14
// baseline (speedup 1.0000x reference)
#include <cuda_runtime.h>
#include <cuda_fp16.h>
#include <math.h>
#include <stdint.h>

// Problem constants
#define T_LEN   4096
#define B_SZ    32
#define D_MODEL 256
#define H_DIM   512
#define KFREQ   128
#define LN_EPS  1e-5f
#define PHSTEP  1.5339807878856412e-3f   // 2*pi/4096
#define NROWS   (B_SZ * T_LEN)           // 131072

// ---------------- device scratch (static; no allocations) ----------------
__device__ float g_ren[B_SZ * KFREQ];
__device__ float g_imn[B_SZ * KFREQ];
__device__ float g_base[B_SZ * H_DIM];
__device__ __align__(16) __half g_w1h[4 * 512 * 40];    // w1b fp16, 4 k32-chunks, [n][k] LDk=40
__device__ __align__(16) __half g_w2h[16 * 256 * 40];   // w2  fp16, 16 k32-chunks, [n][k] LDk=40

// ---------------- helpers ----------------
__device__ __forceinline__ uint32_t smem_u32(const void* p) {
    uint32_t a;
    asm("{ .reg .u64 t; cvta.to.shared.u64 t, %1; cvt.u32.u64 %0, t; }" : "=r"(a) : "l"(p));
    return a;
}
__device__ __forceinline__ void cp16(uint32_t dst, const void* src) {
    asm volatile("cp.async.cg.shared.global [%0], [%1], 16;" :: "r"(dst), "l"(src) : "memory");
}
__device__ __forceinline__ void cp_commit() { asm volatile("cp.async.commit_group;" ::: "memory"); }
__device__ __forceinline__ void cp_wait1()  { asm volatile("cp.async.wait_group 1;" ::: "memory"); }
__device__ __forceinline__ void cp_wait0()  { asm volatile("cp.async.wait_group 0;" ::: "memory"); }

// ldmatrix x4
__device__ __forceinline__ void ldm4(uint32_t& r0, uint32_t& r1, uint32_t& r2, uint32_t& r3,
                                     uint32_t a) {
    asm volatile("ldmatrix.sync.aligned.m8n8.x4.shared.b16 {%0,%1,%2,%3}, [%4];"
                 : "=r"(r0), "=r"(r1), "=r"(r2), "=r"(r3) : "r"(a));
}

// m16n8k16 row.col f32.f16.f16.f32
__device__ __forceinline__ void mma_f16(float* d, const uint32_t* a, uint32_t b0, uint32_t b1) {
    asm volatile(
        "mma.sync.aligned.m16n8k16.row.col.f32.f16.f16.f32 "
        "{%0,%1,%2,%3}, {%4,%5,%6,%7}, {%8,%9}, {%0,%1,%2,%3};"
        : "+f"(d[0]), "+f"(d[1]), "+f"(d[2]), "+f"(d[3])
        : "r"(a[0]), "r"(a[1]), "r"(a[2]), "r"(a[3]), "r"(b0), "r"(b1));
}

// tanh-form GELU (MUFU tanh)
__device__ __forceinline__ float gelu_t(float y) {
    float u = 0.7978845608028654f * __fmaf_rn(0.044715f * y, y * y, y);
    float t;
    asm("tanh.approx.f32 %0, %1;" : "=f"(t) : "f"(u));
    return 0.5f * y * (1.0f + t);
}

// ---------------- kernel: weight prep ----------------
__global__ __launch_bounds__(256) void prep_kernel(const float* __restrict__ w1,
                                                   const float* __restrict__ w2) {
    int i = blockIdx.x * 256 + threadIdx.x;
    if (i < 512 * 128) {                       // w1b: n=0..511, k=0..127
        int n = i >> 7, k = i & 127;
        g_w1h[((k >> 5) * 512 + n) * 40 + (k & 31)] = __float2half_rn(w1[(KFREQ + k) * H_DIM + n]);
    } else {
        int j = i - 512 * 128;                 // w2: n=0..255, k=0..511, k32 chunks
        if (j < 256 * 512) {
            int n = j >> 9, k = j & 511;
            g_w2h[((k >> 5) * 256 + n) * 40 + (k & 31)] = __float2half_rn(w2[k * D_MODEL + n]);
        }
    }
}

// ---------------- kernel: spectral (DFT bins, normalized phase, base) ----------------
#define SPEC_SMEM_FLOATS (T_LEN * 3 + KFREQ)
__global__ __launch_bounds__(256) void spectral_kernel(
    const int* __restrict__ byte_ids,
    const float* __restrict__ freq_bands,
    const float* __restrict__ w1,
    const float* __restrict__ b1)
{
    extern __shared__ float sm[];
    float* sig  = sm;
    float* lc   = sm + T_LEN;
    float* ls   = sm + 2 * T_LEN;
    float* magS = sm + 3 * T_LEN;

    int b   = blockIdx.x;
    int tid = threadIdx.x;

    for (int i = tid; i < T_LEN; i += 256) {
        sig[i] = (float)byte_ids[b * T_LEN + i] * (1.0f / 127.5f) - 1.0f;
        float s, c;
        sincosf((float)i * PHSTEP, &s, &c);
        lc[i] = c; ls[i] = s;
    }
    __syncthreads();

    int warp = tid >> 5, lane = tid & 31;
    for (int f = warp; f < KFREQ; f += 8) {
        float cacc = 0.f, sacc = 0.f;
        int idx  = (lane * f) & (T_LEN - 1);
        int step = (32 * f) & (T_LEN - 1);
        for (int i = lane; i < T_LEN; i += 32) {
            float sv = sig[i];
            cacc += sv * lc[idx];
            sacc += sv * ls[idx];
            idx = (idx + step) & (T_LEN - 1);
        }
        #pragma unroll
        for (int o = 16; o; o >>= 1) {
            cacc += __shfl_xor_sync(0xffffffffu, cacc, o);
            sacc += __shfl_xor_sync(0xffffffffu, sacc, o);
        }
        if (lane == 0) {
            float re = cacc, im = -sacc;
            float hyp = sqrtf(re * re + im * im);
            float rn = 1.0f, in_ = 0.0f;
            if (hyp > 1e-30f) { float inv = 1.0f / hyp; rn = re * inv; in_ = im * inv; }
            g_ren[b * KFREQ + f] = rn;
            g_imn[b * KFREQ + f] = in_;
            magS[f] = hyp * freq_bands[f];
        }
    }
    __syncthreads();

    for (int j = tid; j < H_DIM; j += 256) {
        float acc = b1[j];
        for (int f = 0; f < KFREQ; f++)
            acc += magS[f] * w1[f * H_DIM + j];
        g_base[b * H_DIM + j] = acc;
    }
}

// ---------------- fused kernel: GEMM1 -> LN -> GELU (h in smem) -> GEMM2 -> out ----------------
// Block: 64 rows; grid = 2048 (32 b x 64 tiles); 512 threads (16 warps).
// GEMM1: warps 2m x 8n, tile 32m x 64n. A [64][136]hw, B chunks [512][40]hw x2.
// h: [64][520]hw in smem (66,560 B).
// GEMM2: warps 2m x 8n, tile 32m x 32n; w2 in 16 k32-chunks [256][40]hw, reusing B buffers.
#define F_OFF_A    0
#define F_OFF_B    17408
#define F_OFF_H    99328
#define F_OFF_LN1  165888
#define F_OFF_LN2  167936
#define F_OFF_BASE 169984
#define F_OFF_GAM  172032
#define F_OFF_BET  174080
#define F_OFF_IMN  176128
#define F_OFF_REN  176640
#define F_OFF_B2V  177152
#define F_SMEM_BYTES 178176

__global__ __launch_bounds__(512, 1) void fused_kernel(
    const float* __restrict__ gamma,
    const float* __restrict__ beta,
    const float* __restrict__ b2v,
    float* __restrict__ out)
{
    extern __shared__ char smc[];
    __half* As   = (__half*)(smc + F_OFF_A);
    __half* Hs   = (__half*)(smc + F_OFF_H);
    float*  ln1  = (float*)(smc + F_OFF_LN1);
    float*  ln2  = (float*)(smc + F_OFF_LN2);
    float*  baseS= (float*)(smc + F_OFF_BASE);
    float*  gamS = (float*)(smc + F_OFF_GAM);
    float*  betS = (float*)(smc + F_OFF_BET);
    float*  imnS = (float*)(smc + F_OFF_IMN);
    float*  renS = (float*)(smc + F_OFF_REN);
    float*  b2S  = (float*)(smc + F_OFF_B2V);

    int tid  = threadIdx.x;
    int warp = tid >> 5, lane = tid & 31;
    int g    = lane >> 2, tg = lane & 3;
    int wm   = warp >> 3, wn = warp & 7;      // 2 x 8
    int b    = blockIdx.x >> 6;
    int t0   = (blockIdx.x & 63) * 64;

    // ldmatrix per-lane selectors
    int mrow  = (lane & 7) | (lane & 8);      // 0..15
    int koffA = (lane & 16) ? 16 : 0;
    int nrow  = lane & 7;
    int nadd  = (lane & 16) ? 8 : 0;
    int koffB = (lane & 8) ? 16 : 0;

    if (tid < 128) { imnS[tid] = g_imn[b * KFREQ + tid]; renS[tid] = g_ren[b * KFREQ + tid]; }
    baseS[tid] = g_base[b * H_DIM + tid];
    gamS[tid]  = gamma[tid];
    betS[tid]  = beta[tid];
    if (tid < 256) b2S[tid] = b2v[tid];

    uint32_t bbuf[2] = { smem_u32(smc + F_OFF_B), smem_u32(smc + F_OFF_B + 40960) };
    // issue w1 chunk 0 (overlaps with A generation)
    {
        const char* src = (const char*)g_w1h;
        #pragma unroll
        for (int i = 0; i < 5; i++) { int e = tid + i * 512; cp16(bbuf[0] + e * 16, src + e * 16); }
        cp_commit();
    }
    __syncthreads();   // imnS/renS ready

    // generate A (64 x 128) fp16, LDk=136 hw
    for (int e = tid; e < 64 * 128; e += 512) {
        int m = e >> 7, k = e & 127;
        int idx = ((t0 + m) * k) & (T_LEN - 1);
        if (idx >= T_LEN / 2) idx -= T_LEN;
        float s, c;
        __sincosf((float)idx * PHSTEP, &s, &c);
        As[m * 136 + k] = __float2half_rn(imnS[k] * c + renS[k] * s);
    }

    float acc[2][8][4];
    #pragma unroll
    for (int mt = 0; mt < 2; mt++)
        #pragma unroll
        for (int nt = 0; nt < 8; nt++)
            #pragma unroll
            for (int d = 0; d < 4; d++) acc[mt][nt][d] = 0.f;

    uint32_t aAdr = smem_u32(As) + (32 * wm + mrow) * 272 + koffA;
    uint32_t bOff = (uint32_t)(wn * 64 + nrow + nadd) * 80 + koffB;

    // ================= GEMM1 =================
    for (int c = 0; c < 4; c++) {
        if (c < 3) {
            const char* src = (const char*)g_w1h + (c + 1) * 40960;
            uint32_t dst = bbuf[(c + 1) & 1];
            #pragma unroll
            for (int i = 0; i < 5; i++) { int e = tid + i * 512; cp16(dst + e * 16, src + e * 16); }
            cp_commit();
            cp_wait1();
        } else {
            cp_wait0();
        }
        __syncthreads();

        uint32_t bbase = bbuf[c & 1] + bOff;
        uint32_t abase = aAdr + c * 64;
        #pragma unroll
        for (int ks = 0; ks < 2; ks++) {
            uint32_t A0[4], A1[4];
            ldm4(A0[0], A0[1], A0[2], A0[3], abase + ks * 32);
            ldm4(A1[0], A1[1], A1[2], A1[3], abase + 16 * 272 + ks * 32);
            #pragma unroll
            for (int ntp = 0; ntp < 4; ntp++) {
                uint32_t b0, b1, b2, b3;
                ldm4(b0, b1, b2, b3, bbase + ntp * (16 * 80) + ks * 32);
                mma_f16(acc[0][2 * ntp],     A0, b0, b1);
                mma_f16(acc[1][2 * ntp],     A1, b0, b1);
                mma_f16(acc[0][2 * ntp + 1], A0, b2, b3);
                mma_f16(acc[1][2 * ntp + 1], A1, b2, b3);
            }
        }
        __syncthreads();
    }

    // prefetch w2 chunk 0 into buf0 (hides under LN/GELU epilogue)
    {
        const char* wb = (const char*)g_w2h;
        for (int e = tid; e < 1280; e += 512) cp16(bbuf[0] + e * 16, wb + e * 16);
        cp_commit();
    }

    // ---- +base, LN stats ----
    #pragma unroll
    for (int mt = 0; mt < 2; mt++)
        #pragma unroll
        for (int nt = 0; nt < 8; nt++) {
            int j0 = wn * 64 + nt * 8 + 2 * tg;
            acc[mt][nt][0] += baseS[j0];
            acc[mt][nt][1] += baseS[j0 + 1];
            acc[mt][nt][2] += baseS[j0];
            acc[mt][nt][3] += baseS[j0 + 1];
        }

    #pragma unroll
    for (int mt = 0; mt < 2; mt++)
        #pragma unroll
        for (int h = 0; h < 2; h++) {
            float s1 = 0.f, s2 = 0.f;
            #pragma unroll
            for (int nt = 0; nt < 8; nt++) {
                float v0 = acc[mt][nt][2 * h], v1 = acc[mt][nt][2 * h + 1];
                s1 += v0 + v1; s2 += v0 * v0 + v1 * v1;
            }
            s1 += __shfl_xor_sync(0xffffffffu, s1, 1); s2 += __shfl_xor_sync(0xffffffffu, s2, 1);
            s1 += __shfl_xor_sync(0xffffffffu, s1, 2); s2 += __shfl_xor_sync(0xffffffffu, s2, 2);
            if (tg == 0) {
                int r = 32 * wm + 16 * mt + g + 8 * h;
                ln1[r * 8 + wn] = s1;
                ln2[r * 8 + wn] = s2;
            }
        }
    __syncthreads();

    float mean[2][2], rstd[2][2];
    #pragma unroll
    for (int mt = 0; mt < 2; mt++)
        #pragma unroll
        for (int h = 0; h < 2; h++) {
            int r = 32 * wm + 16 * mt + g + 8 * h;
            float t1 = 0.f, t2 = 0.f;
            #pragma unroll
            for (int w = 0; w < 8; w++) { t1 += ln1[r * 8 + w]; t2 += ln2[r * 8 + w]; }
            float mu = t1 * (1.0f / H_DIM);
            float va = t2 * (1.0f / H_DIM) - mu * mu;
            mean[mt][h] = mu;
            rstd[mt][h] = rsqrtf(va + LN_EPS);
        }

    // ---- GELU (tanh) -> h into smem [64][520]hw ----
    #pragma unroll
    for (int mt = 0; mt < 2; mt++) {
        int r0 = 32 * wm + 16 * mt + g;
        #pragma unroll
        for (int nt = 0; nt < 8; nt++) {
            int j0 = wn * 64 + nt * 8 + 2 * tg;
            float ga = gamS[j0], gb = gamS[j0 + 1], ba = betS[j0], bb = betS[j0 + 1];
            float y00 = (acc[mt][nt][0] - mean[mt][0]) * rstd[mt][0] * ga + ba;
            float y01 = (acc[mt][nt][1] - mean[mt][0]) * rstd[mt][0] * gb + bb;
            float y10 = (acc[mt][nt][2] - mean[mt][1]) * rstd[mt][1] * ga + ba;
            float y11 = (acc[mt][nt][3] - mean[mt][1]) * rstd[mt][1] * gb + bb;
            *(__half2*)&Hs[r0 * 520 + j0]       = __floats2half2_rn(gelu_t(y00), gelu_t(y01));
            *(__half2*)&Hs[(r0 + 8) * 520 + j0] = __floats2half2_rn(gelu_t(y10), gelu_t(y11));
        }
    }

    // ================= GEMM2: out(64x256) = h(64x512) @ W2(512x256) =================
    float acc2[2][4][4];
    #pragma unroll
    for (int mt = 0; mt < 2; mt++)
        #pragma unroll
        for (int nt = 0; nt < 4; nt++)
            #pragma unroll
            for (int d = 0; d < 4; d++) acc2[mt][nt][d] = 0.f;

    uint32_t aAdr2 = smem_u32(Hs) + (32 * wm + mrow) * 1040 + koffA;
    uint32_t bOff2 = (uint32_t)(wn * 32 + nrow + nadd) * 80 + koffB;

    for (int c = 0; c < 16; c++) {
        if (c < 15) {
            const char* wb = (const char*)g_w2h + (size_t)(c + 1) * 20480;
            uint32_t dst = bbuf[(c + 1) & 1];
            for (int e = tid; e < 1280; e += 512) cp16(dst + e * 16, wb + e * 16);
            cp_commit();
            cp_wait1();
        } else {
            cp_wait0();
        }
        __syncthreads();   // also orders h STS (c=0) before ldmatrix reads

        uint32_t bbase = bbuf[c & 1] + bOff2;
        uint32_t abase = aAdr2 + c * 64;
        #pragma unroll
        for (int ks = 0; ks < 2; ks++) {
            uint32_t A0[4], A1[4];
            ldm4(A0[0], A0[1], A0[2], A0[3], abase + ks * 32);
            ldm4(A1[0], A1[1], A1[2], A1[3], abase + 16 * 1040 + ks * 32);
            #pragma unroll
            for (int ntp = 0; ntp < 2; ntp++) {
                uint32_t b0, b1, b2, b3;
                ldm4(b0, b1, b2, b3, bbase + ntp * (16 * 80) + ks * 32);
                mma_f16(acc2[0][2 * ntp],     A0, b0, b1);
                mma_f16(acc2[1][2 * ntp],     A1, b0, b1);
                mma_f16(acc2[0][2 * ntp + 1], A0, b2, b3);
                mma_f16(acc2[1][2 * ntp + 1], A1, b2, b3);
            }
        }
        __syncthreads();
    }

    // epilogue: +b2, store float2
    #pragma unroll
    for (int mt = 0; mt < 2; mt++) {
        size_t r0 = (size_t)(b * T_LEN + t0 + 32 * wm + 16 * mt + g);
        size_t r1 = r0 + 8;
        #pragma unroll
        for (int nt = 0; nt < 4; nt++) {
            int j0 = wn * 32 + nt * 8 + 2 * tg;
            float ba = b2S[j0], bb = b2S[j0 + 1];
            *(float2*)&out[r0 * D_MODEL + j0] = make_float2(acc2[mt][nt][0] + ba, acc2[mt][nt][1] + bb);
            *(float2*)&out[r1 * D_MODEL + j0] = make_float2(acc2[mt][nt][2] + ba, acc2[mt][nt][3] + bb);
        }
    }
}

// ---------------- launch ----------------
extern "C" void kernel_launch(void* const* d_in, const int* in_sizes, int n_in,
                              void* d_out, int out_size) {
    const int*   byte_ids = (const int*)  d_in[0];
    const float* fb       = (const float*)d_in[1];
    const float* w1       = (const float*)d_in[2];
    const float* b1       = (const float*)d_in[3];
    const float* gamma    = (const float*)d_in[4];
    const float* beta     = (const float*)d_in[5];
    const float* w2       = (const float*)d_in[6];
    const float* b2v      = (const float*)d_in[7];
    float* out = (float*)d_out;

    (void)in_sizes; (void)n_in; (void)out_size;

    cudaFuncSetAttribute(spectral_kernel, cudaFuncAttributeMaxDynamicSharedMemorySize,
                         SPEC_SMEM_FLOATS * (int)sizeof(float));
    cudaFuncSetAttribute(fused_kernel, cudaFuncAttributeMaxDynamicSharedMemorySize, F_SMEM_BYTES);

    prep_kernel<<<768, 256>>>(w1, w2);
    spectral_kernel<<<B_SZ, 256, SPEC_SMEM_FLOATS * sizeof(float)>>>(byte_ids, fb, w1, b1);
    fused_kernel<<<B_SZ * (T_LEN / 64), 512, F_SMEM_BYTES>>>(gamma, beta, b2v, out);
}